// round 8
// baseline (speedup 1.0000x reference)
#include <cuda_runtime.h>
#include <math.h>

#define HW   (128*128)
#define CHW  (16*HW)
typedef unsigned long long ull;

// ---------------- scratch ----------------
__device__ float g_b1[7*CHW];    // conv1 out (3) / conv3 out (7)
__device__ float g_b2[5*CHW];    // conv2 out (5) -- kept for final skip recompute
__device__ float g_b3[9*CHW];    // conv4 out (9)
__device__ float g_sum[4*16];
__device__ float g_sumsq[4*16];

struct Taps { int isl[9][3]; int msk[9][3]; float mult[9]; };

// ---------------- f32x2 helpers ----------------
__device__ __forceinline__ ull pack2(float v){
    ull r; asm("mov.b64 %0,{%1,%2};" : "=l"(r) : "f"(v), "f"(v)); return r;
}
__device__ __forceinline__ void fma2(ull &d, ull a, ull b){
    asm("fma.rn.f32x2 %0,%1,%2,%0;" : "+l"(d) : "l"(a), "l"(b));
}
__device__ __forceinline__ void unpack2(ull a, float &x, float &y){
    asm("mov.b64 {%0,%1},%2;" : "=f"(x), "=f"(y) : "l"(a));
}

// ---------------- fused conv stage ----------------
// MODE 0: raw input. MODE 1: relu(fma(x,a,b)), a=istd, b=-mean*istd finalized
// inline from raw atomic sums. MODE 2: relu(fma(x,a,b) + skip).
// Halo: transform only in-range pixels; out-of-range pad = 0.
// Block: 128 threads (8 z x 16 y), thread = 1 px x 16 co (8 f32x2 accs).
// Tile 8x16 px; grid x = 128 tiles, y = output slice. 8 blocks/SM resident.
template<int MODE>
__global__ __launch_bounds__(128, 8) void conv_stage(
    const float* __restrict__ in, size_t in_stride,
    float* __restrict__ out,
    const float* __restrict__ w, const float* __restrict__ bias,
    const float* __restrict__ prev_s, const float* __restrict__ prev_q,
    const float* __restrict__ skip,
    float* __restrict__ stat_s, float* __restrict__ stat_q,
    Taps tp)
{
    __shared__ float s_w[16*9*16];      // [ci][k][co], mask-summed over kx
    __shared__ float s_in[16*180];      // [ci][r(10)][c(18)]
    __shared__ float s_a[16], s_b[16];
    __shared__ float s_red[4][32];

    const int osl = blockIdx.y;
    const int tile = blockIdx.x;
    const int tz0 = (tile >> 3) << 3;   // 16 z-tiles of 8
    const int ty0 = (tile &  7) << 4;   // 8 y-tiles of 16
    const int tid = threadIdx.x;
    const int tz  = tid >> 4;          // 0..7
    const int ty  = tid & 15;          // 0..15

    // inline finalize of previous stage's instance-norm stats
    if (MODE > 0 && tid < 16){
        double sd = (double)prev_s[tid];
        double qd = (double)prev_q[tid];
        double mean = sd / 2097152.0;
        double var  = qd / 2097152.0 - mean*mean;
        double isd  = 1.0 / sqrt(var + 1e-5);
        s_a[tid] = (float)isd;
        s_b[tid] = (float)(-mean*isd);
    }

    // tile-load slots: slot0 = tid (<180 always), slot1 = tid+128 (tid<52)
    int px0, px1; bool ok0, ok1;
    {
        int r = tid/18, c = tid - r*18;
        int gz = tz0 + r - 1, gy = ty0 + c - 1;
        ok0 = ((unsigned)gz < 128u) && ((unsigned)gy < 128u);
        px0 = gz*128 + gy;
        int j = tid + 128;
        r = j/18; c = j - r*18;
        gz = tz0 + r - 1; gy = ty0 + c - 1;
        ok1 = (j < 180) && ((unsigned)gz < 128u) && ((unsigned)gy < 128u);
        px1 = gz*128 + gy;
    }

    ull acc[8];
#pragma unroll
    for (int t=0;t<8;t++) acc[t] = 0ull;

    for (int e=0; e<3; e++){
        const int isl = tp.isl[osl][e];
        if (isl < 0) continue;
        const int m = tp.msk[osl][e];
        __syncthreads();
        // weights (summed over kx taps sharing this input slice): 2304/128 = 18
#pragma unroll
        for (int it=0; it<18; it++){
            int idx = tid + it*128;
            int co = idx & 15;
            int k  = (idx >> 4) % 9;
            int ci = idx / 144;
            int base = ((co*16+ci)*9 + k)*3;
            float wv = 0.f;
            if (m & 1) wv += w[base+0];
            if (m & 2) wv += w[base+1];
            if (m & 4) wv += w[base+2];
            s_w[idx] = wv;
        }
        // input tile: ci batched in groups of 4 (keeps regs low, MLP ~4-16)
        const float* ip = in + (size_t)isl*in_stride;
#pragma unroll
        for (int cg=0; cg<16; cg+=4){
            float xv[4];
#pragma unroll
            for (int u2=0; u2<4; u2++)
                xv[u2] = ok0 ? ip[(cg+u2)*HW + px0] : 0.f;
            if (MODE == 2){
                float sv[4];
#pragma unroll
                for (int u2=0; u2<4; u2++)
                    sv[u2] = ok0 ? skip[(cg+u2)*HW + px0] : 0.f;
#pragma unroll
                for (int u2=0; u2<4; u2++){
                    float t = fmaxf(fmaf(xv[u2], s_a[cg+u2], s_b[cg+u2]) + sv[u2], 0.f);
                    s_in[(cg+u2)*180 + tid] = ok0 ? t : 0.f;
                }
            } else if (MODE == 1){
#pragma unroll
                for (int u2=0; u2<4; u2++){
                    float t = fmaxf(fmaf(xv[u2], s_a[cg+u2], s_b[cg+u2]), 0.f);
                    s_in[(cg+u2)*180 + tid] = ok0 ? t : 0.f;
                }
            } else {
#pragma unroll
                for (int u2=0; u2<4; u2++)
                    s_in[(cg+u2)*180 + tid] = xv[u2];
            }
        }
        if (tid < 52){
#pragma unroll
            for (int cg=0; cg<16; cg+=4){
                float xv[4];
#pragma unroll
                for (int u2=0; u2<4; u2++)
                    xv[u2] = ok1 ? ip[(cg+u2)*HW + px1] : 0.f;
                if (MODE == 2){
                    float sv[4];
#pragma unroll
                    for (int u2=0; u2<4; u2++)
                        sv[u2] = ok1 ? skip[(cg+u2)*HW + px1] : 0.f;
#pragma unroll
                    for (int u2=0; u2<4; u2++){
                        float t = fmaxf(fmaf(xv[u2], s_a[cg+u2], s_b[cg+u2]) + sv[u2], 0.f);
                        s_in[(cg+u2)*180 + tid + 128] = ok1 ? t : 0.f;
                    }
                } else if (MODE == 1){
#pragma unroll
                    for (int u2=0; u2<4; u2++){
                        float t = fmaxf(fmaf(xv[u2], s_a[cg+u2], s_b[cg+u2]), 0.f);
                        s_in[(cg+u2)*180 + tid + 128] = ok1 ? t : 0.f;
                    }
                } else {
#pragma unroll
                    for (int u2=0; u2<4; u2++)
                        s_in[(cg+u2)*180 + tid + 128] = xv[u2];
                }
            }
        }
        __syncthreads();

        // compute: 1 px x 16 co; values loaded per-k inline (low reg pressure)
        const float* sbase = s_in + tz*18 + ty;
#pragma unroll 1
        for (int ci=0; ci<16; ci++){
            const float* si = sbase + ci*180;
            const float* wbase = s_w + ci*144;
#pragma unroll
            for (int k=0; k<9; k++){
                ull pv = pack2(si[(k/3)*18 + (k%3)]);
                const ulonglong2* wq = reinterpret_cast<const ulonglong2*>(wbase + k*16);
                ulonglong2 wa = wq[0], wb = wq[1];
                fma2(acc[0],pv,wa.x); fma2(acc[1],pv,wa.y);
                fma2(acc[2],pv,wb.x); fma2(acc[3],pv,wb.y);
                wa = wq[2]; wb = wq[3];
                fma2(acc[4],pv,wa.x); fma2(acc[5],pv,wa.y);
                fma2(acc[6],pv,wb.x); fma2(acc[7],pv,wb.y);
            }
        }
    }

    // epilogue: bias, store, fused stats
    float s[16], q[16];
    const int oz = tz0 + tz, oy = ty0 + ty;
    const int pix = oz*128 + oy;
    float* op = out + (size_t)osl*CHW;
#pragma unroll
    for (int t=0;t<8;t++){
        float x,y; unpack2(acc[t], x, y);
        float v0 = x + bias[2*t];
        float v1 = y + bias[2*t+1];
        op[(2*t)*HW   + pix] = v0;
        op[(2*t+1)*HW + pix] = v1;
        s[2*t]   = v0;  q[2*t]   = v0*v0;
        s[2*t+1] = v1;  q[2*t+1] = v1*v1;
    }
#pragma unroll
    for (int co=0;co<16;co++){
#pragma unroll
        for (int o=16;o>0;o>>=1){
            s[co] += __shfl_xor_sync(0xffffffffu, s[co], o);
            q[co] += __shfl_xor_sync(0xffffffffu, q[co], o);
        }
    }
    __syncthreads();
    if ((tid & 31) == 0){
        const int wd = tid >> 5;
#pragma unroll
        for (int co=0;co<16;co++){
            s_red[wd][co]    = s[co];
            s_red[wd][16+co] = q[co];
        }
    }
    __syncthreads();
    if (tid < 32){
        float t4 = s_red[0][tid] + s_red[1][tid] + s_red[2][tid] + s_red[3][tid];
        t4 *= tp.mult[osl];
        if (tid < 16) atomicAdd(&stat_s[tid], t4);
        else          atomicAdd(&stat_q[tid-16], t4);
    }
}

// ---------------- stats zero ----------------
__global__ void zero_stats(){
    int i = threadIdx.x;
    if (i < 64){ g_sum[i]=0.f; g_sumsq[i]=0.f; }
}

// ---------------- fused final elementwise + forward projection ----------------
// final[sl] = relu( norm3(s3[sl]) + relu( norm1(s2[skm[sl]]) + V ) )
// out[c,0,z,u] = weighted slice sum at (z,y=u)
// out[c,1,z,u] = column sum over y of slice sel(u); u==0 sums only y=0..63
//   (reference fp32: x=+-3.9e-15 at uu=0, valid mask kills y in [64,127]).
__global__ __launch_bounds__(128) void forward_proj(
    const float* __restrict__ s3, const float* __restrict__ s2,
    const float* __restrict__ V, float* __restrict__ out)
{
    __shared__ float red[9][4];
    __shared__ float rs[9];
    const int c = blockIdx.x >> 7, z = blockIdx.x & 127;
    const int u = threadIdx.x;
    const int   skm[9]  = {0,1,2,2,2,2,2,3,4};
    const float mult[9] = {1.f,1.f,1.f,1.f,120.f,1.f,1.f,1.f,1.f};

    // inline stats finalize: bank1 (A2 output) and bank3 (B2 output)
    double sd1 = (double)g_sum[16+c], qd1 = (double)g_sumsq[16+c];
    double me1 = sd1/2097152.0;
    double i1d = 1.0/sqrt(qd1/2097152.0 - me1*me1 + 1e-5);
    const float i1 = (float)i1d, b1c = (float)(-me1*i1d);
    double sd3 = (double)g_sum[48+c], qd3 = (double)g_sumsq[48+c];
    double me3 = sd3/2097152.0;
    double i3d = 1.0/sqrt(qd3/2097152.0 - me3*me3 + 1e-5);
    const float i3 = (float)i3d, b3c = (float)(-me3*i3d);

    const int pix = z*128 + u;
    const float vb = V[c*HW + pix];

    float vals[9]; float s0 = 0.f;
#pragma unroll
    for (int sdx=0; sdx<9; sdx++){
        float t2 = s2[(size_t)(skm[sdx]*16 + c)*HW + pix];
        float sk = fmaxf(fmaf(t2, i1, b1c) + vb, 0.f);
        float t3 = s3[(size_t)(sdx*16 + c)*HW + pix];
        float fv = fmaxf(fmaf(t3, i3, b3c) + sk, 0.f);
        vals[sdx] = fv;
        s0 += mult[sdx]*fv;
    }
    out[(c*2+0)*HW + pix] = s0;

    const int lane = u & 31, wid = u >> 5;
#pragma unroll
    for (int sdx=0; sdx<9; sdx++){
        float v = vals[sdx];
#pragma unroll
        for (int o=16;o>0;o>>=1) v += __shfl_xor_sync(0xffffffffu, v, o);
        if (lane==0) red[sdx][wid]=v;
    }
    __syncthreads();
    if (u < 9) rs[u] = red[u][0]+red[u][1]+red[u][2]+red[u][3];
    __syncthreads();
    const int sl = (u<4) ? u : (u>123 ? u-119 : 4);
    float o1 = (u==0) ? (red[0][0]+red[0][1]) : rs[sl];
    out[(c*2+1)*HW + pix] = o1;
}

// ---------------- launch ----------------
extern "C" void kernel_launch(void* const* d_in, const int* in_sizes, int n_in,
                              void* d_out, int out_size)
{
    (void)in_sizes; (void)n_in; (void)out_size;
    const float* V    = (const float*)d_in[0];
    const float* w_a1 = (const float*)d_in[1];
    const float* b_a1 = (const float*)d_in[2];
    const float* w_a2 = (const float*)d_in[3];
    const float* b_a2 = (const float*)d_in[4];
    const float* w_b1 = (const float*)d_in[5];
    const float* b_b1 = (const float*)d_in[6];
    const float* w_b2 = (const float*)d_in[7];
    const float* b_b2 = (const float*)d_in[8];
    float* out = (float*)d_out;

    float *b1,*b2,*b3,*gsum,*gsq;
    cudaGetSymbolAddress((void**)&b1,    g_b1);
    cudaGetSymbolAddress((void**)&b2,    g_b2);
    cudaGetSymbolAddress((void**)&b3,    g_b3);
    cudaGetSymbolAddress((void**)&gsum,  g_sum);
    cudaGetSymbolAddress((void**)&gsq,   g_sumsq);

    // merged tap tables: (input slice, kx bitmask) per output slice
    Taps tA1 = {
        { {0,-1,-1},{0,-1,-1},{0,-1,-1} },
        { {6,0,0},{7,0,0},{3,0,0} },
        { 1.f,126.f,1.f }
    };
    Taps tA2 = {
        { {0,1,-1},{0,1,-1},{1,-1,-1},{1,2,-1},{1,2,-1} },
        { {2,4,0},{1,6,0},{7,0,0},{3,4,0},{1,2,0} },
        { 1.f,1.f,124.f,1.f,1.f }
    };
    Taps tB1 = {
        { {0,1,-1},{0,1,2},{1,2,-1},{2,-1,-1},{2,3,-1},{2,3,4},{3,4,-1} },
        { {2,4,0},{1,2,4},{1,6,0},{7,0,0},{3,4,0},{1,2,4},{1,2,0} },
        { 1.f,1.f,1.f,122.f,1.f,1.f,1.f }
    };
    Taps tB2 = {
        { {0,1,-1},{0,1,2},{1,2,3},{2,3,-1},{3,-1,-1},{3,4,-1},{3,4,5},{4,5,6},{5,6,-1} },
        { {2,4,0},{1,2,4},{1,2,4},{1,6,0},{7,0,0},{3,4,0},{1,2,4},{1,2,4},{1,2,0} },
        { 1.f,1.f,1.f,1.f,120.f,1.f,1.f,1.f,1.f }
    };

    zero_stats<<<1,64>>>();

    // A1: raw V (slice stride 0) -> b1 (3 slices), stats bank 0
    conv_stage<0><<<dim3(128,3),128>>>(V, 0, b1, w_a1, b_a1,
                                       nullptr, nullptr, nullptr,
                                       gsum+0, gsq+0, tA1);

    // A2: norm_relu(b1, bank0) -> b2 (5), stats bank 1
    conv_stage<1><<<dim3(128,5),128>>>(b1, CHW, b2, w_a2, b_a2,
                                       gsum+0, gsq+0, nullptr,
                                       gsum+16, gsq+16, tA2);

    // B1: relu(norm(b2, bank1) + V) -> b1 (7), stats bank 2
    conv_stage<2><<<dim3(128,7),128>>>(b2, CHW, b1, w_b1, b_b1,
                                       gsum+16, gsq+16, V,
                                       gsum+32, gsq+32, tB1);

    // B2: norm_relu(b1, bank2) -> b3 (9), stats bank 3
    conv_stage<1><<<dim3(128,9),128>>>(b1, CHW, b3, w_b2, b_b2,
                                       gsum+32, gsq+32, nullptr,
                                       gsum+48, gsq+48, tB2);

    // fused final norm+skip+relu + both projections (bank1+bank3 inline)
    forward_proj<<<16*128,128>>>(b3, b2, V, out);
}

// round 9
// speedup vs baseline: 1.2928x; 1.2928x over previous
#include <cuda_runtime.h>
#include <math.h>

#define HW   (128*128)
#define CHW  (16*HW)
typedef unsigned long long ull;

// ---------------- scratch ----------------
__device__ float g_b1[7*CHW];    // conv1 out (3) / conv3 out (7)
__device__ float g_b2[5*CHW];    // conv2 out (5) -- kept for final skip recompute
__device__ float g_b3[9*CHW];    // conv4 out (9)
__device__ float g_sum[4*16];
__device__ float g_sumsq[4*16];

struct Taps { int isl[9][3]; int msk[9][3]; float mult[9]; };

// ---------------- f32x2 helpers ----------------
__device__ __forceinline__ ull pack2(float v){
    ull r; asm("mov.b64 %0,{%1,%2};" : "=l"(r) : "f"(v), "f"(v)); return r;
}
__device__ __forceinline__ void fma2(ull &d, ull a, ull b){
    asm("fma.rn.f32x2 %0,%1,%2,%0;" : "+l"(d) : "l"(a), "l"(b));
}
__device__ __forceinline__ void unpack2(ull a, float &x, float &y){
    asm("mov.b64 {%0,%1},%2;" : "=f"(x), "=f"(y) : "l"(a));
}

// ---------------- fused conv stage ----------------
// MODE 0: raw input. MODE 1: relu(fma(x,a,b)), a=istd, b=-mean*istd finalized
// inline from raw atomic sums. MODE 2: relu(fma(x,a,b) + skip).
// Halo: transform only in-range pixels; out-of-range pad = 0.
// Block: 128 threads = 32 pixel-slots x 4 co-groups. Thread = 1x4 px strip x
// 4 co (8 f32x2 accs). Weight traffic: 1 LDS.128 per (ci,k) per thread.
// Tile 8z x 16y; grid x = 128 tiles, y = output slice. 8 blocks/SM.
template<int MODE>
__global__ __launch_bounds__(128, 8) void conv_stage(
    const float* __restrict__ in, size_t in_stride,
    float* __restrict__ out,
    const float* __restrict__ w, const float* __restrict__ bias,
    const float* __restrict__ prev_s, const float* __restrict__ prev_q,
    const float* __restrict__ skip,
    float* __restrict__ stat_s, float* __restrict__ stat_q,
    Taps tp)
{
    __shared__ float s_w[16*9*16];      // [ci][k][co], mask-summed over kx
    __shared__ float s_in[16*180];      // [ci][r(10)][c(18)]
    __shared__ float s_a[16], s_b[16];
    __shared__ float s_red[4][4][8];    // [warp][cg][4 s + 4 q]

    const int osl = blockIdx.y;
    const int tile = blockIdx.x;
    const int tz0 = (tile >> 3) << 3;   // 16 z-tiles of 8
    const int ty0 = (tile &  7) << 4;   // 8 y-tiles of 16
    const int tid = threadIdx.x;
    const int cg   = tid & 3;           // co-group: co = cg*4 .. cg*4+3
    const int slot = tid >> 2;          // 0..31 pixel slot
    const int tz   = slot >> 2;         // 0..7
    const int tyq  = slot & 3;          // 0..3 -> y = tyq*4 .. tyq*4+3

    // inline finalize of previous stage's instance-norm stats
    if (MODE > 0 && tid < 16){
        double sd = (double)prev_s[tid];
        double qd = (double)prev_q[tid];
        double mean = sd / 2097152.0;
        double var  = qd / 2097152.0 - mean*mean;
        double isd  = 1.0 / sqrt(var + 1e-5);
        s_a[tid] = (float)isd;
        s_b[tid] = (float)(-mean*isd);
    }

    // tile-load slots: slot0 = tid (<180 always), slot1 = tid+128 (tid<52)
    int px0, px1; bool ok0, ok1;
    {
        int r = tid/18, c = tid - r*18;
        int gz = tz0 + r - 1, gy = ty0 + c - 1;
        ok0 = ((unsigned)gz < 128u) && ((unsigned)gy < 128u);
        px0 = gz*128 + gy;
        int j = tid + 128;
        r = j/18; c = j - r*18;
        gz = tz0 + r - 1; gy = ty0 + c - 1;
        ok1 = (j < 180) && ((unsigned)gz < 128u) && ((unsigned)gy < 128u);
        px1 = gz*128 + gy;
    }

    ull acc[2][4];                      // [co-pair][py]
#pragma unroll
    for (int p=0;p<2;p++)
#pragma unroll
    for (int py=0;py<4;py++) acc[p][py] = 0ull;

    for (int e=0; e<3; e++){
        const int isl = tp.isl[osl][e];
        if (isl < 0) continue;
        const int m = tp.msk[osl][e];
        __syncthreads();
        // weights (summed over kx taps sharing this input slice): 2304/128=18
#pragma unroll
        for (int it=0; it<18; it++){
            int idx = tid + it*128;
            int co = idx & 15;
            int k  = (idx >> 4) % 9;
            int ci = idx / 144;
            int base = ((co*16+ci)*9 + k)*3;
            float wv = 0.f;
            if (m & 1) wv += w[base+0];
            if (m & 2) wv += w[base+1];
            if (m & 4) wv += w[base+2];
            s_w[idx] = wv;
        }
        // input tile: ci batched in groups of 4 (MLP ~4-16)
        const float* ip = in + (size_t)isl*in_stride;
#pragma unroll
        for (int cgl=0; cgl<16; cgl+=4){
            float xv[4];
#pragma unroll
            for (int u2=0; u2<4; u2++)
                xv[u2] = ok0 ? ip[(cgl+u2)*HW + px0] : 0.f;
            if (MODE == 2){
                float svv[4];
#pragma unroll
                for (int u2=0; u2<4; u2++)
                    svv[u2] = ok0 ? skip[(cgl+u2)*HW + px0] : 0.f;
#pragma unroll
                for (int u2=0; u2<4; u2++){
                    float t = fmaxf(fmaf(xv[u2], s_a[cgl+u2], s_b[cgl+u2]) + svv[u2], 0.f);
                    s_in[(cgl+u2)*180 + tid] = ok0 ? t : 0.f;
                }
            } else if (MODE == 1){
#pragma unroll
                for (int u2=0; u2<4; u2++){
                    float t = fmaxf(fmaf(xv[u2], s_a[cgl+u2], s_b[cgl+u2]), 0.f);
                    s_in[(cgl+u2)*180 + tid] = ok0 ? t : 0.f;
                }
            } else {
#pragma unroll
                for (int u2=0; u2<4; u2++)
                    s_in[(cgl+u2)*180 + tid] = xv[u2];
            }
        }
        if (tid < 52){
#pragma unroll
            for (int cgl=0; cgl<16; cgl+=4){
                float xv[4];
#pragma unroll
                for (int u2=0; u2<4; u2++)
                    xv[u2] = ok1 ? ip[(cgl+u2)*HW + px1] : 0.f;
                if (MODE == 2){
                    float svv[4];
#pragma unroll
                    for (int u2=0; u2<4; u2++)
                        svv[u2] = ok1 ? skip[(cgl+u2)*HW + px1] : 0.f;
#pragma unroll
                    for (int u2=0; u2<4; u2++){
                        float t = fmaxf(fmaf(xv[u2], s_a[cgl+u2], s_b[cgl+u2]) + svv[u2], 0.f);
                        s_in[(cgl+u2)*180 + tid + 128] = ok1 ? t : 0.f;
                    }
                } else if (MODE == 1){
#pragma unroll
                    for (int u2=0; u2<4; u2++){
                        float t = fmaxf(fmaf(xv[u2], s_a[cgl+u2], s_b[cgl+u2]), 0.f);
                        s_in[(cgl+u2)*180 + tid + 128] = ok1 ? t : 0.f;
                    }
                } else {
#pragma unroll
                    for (int u2=0; u2<4; u2++)
                        s_in[(cgl+u2)*180 + tid + 128] = xv[u2];
                }
            }
        }
        __syncthreads();

        // compute: 4 px x 4 co. Per (ci,k): 1 LDS.128 of weights.
        const float* sbase = s_in + tz*18 + tyq*4;
        const float* wb    = s_w  + cg*4;
#pragma unroll 1
        for (int ci=0; ci<16; ci++){
            const float* si    = sbase + ci*180;
            const float* wbase = wb    + ci*144;
#pragma unroll
            for (int kz=0; kz<3; kz++){
                const float* row = si + kz*18;
                ull pv[6];
#pragma unroll
                for (int j=0;j<6;j++) pv[j] = pack2(row[j]);
#pragma unroll
                for (int ky=0; ky<3; ky++){
                    ulonglong2 wq = *reinterpret_cast<const ulonglong2*>(wbase + (kz*3+ky)*16);
#pragma unroll
                    for (int py=0; py<4; py++){
                        fma2(acc[0][py], pv[ky+py], wq.x);
                        fma2(acc[1][py], pv[ky+py], wq.y);
                    }
                }
            }
        }
    }

    // epilogue: bias, vectorized store, fused stats
    const int oz  = tz0 + tz;
    const int oy0 = ty0 + tyq*4;
    float* op = out + (size_t)osl*CHW + oz*128 + oy0;

    float sv[4], qv[4];
#pragma unroll
    for (int p=0; p<2; p++){
        const int c0 = cg*4 + 2*p, c1 = c0 + 1;
        const float b0 = bias[c0], b1 = bias[c1];
        float r0[4], r1[4];
#pragma unroll
        for (int py=0; py<4; py++){
            float x,y; unpack2(acc[p][py], x, y);
            r0[py] = x + b0;
            r1[py] = y + b1;
        }
        *reinterpret_cast<float4*>(op + c0*HW) = make_float4(r0[0],r0[1],r0[2],r0[3]);
        *reinterpret_cast<float4*>(op + c1*HW) = make_float4(r1[0],r1[1],r1[2],r1[3]);
        float s0=0.f,q0=0.f,s1=0.f,q1=0.f;
#pragma unroll
        for (int py=0; py<4; py++){
            s0 += r0[py]; q0 += r0[py]*r0[py];
            s1 += r1[py]; q1 += r1[py]*r1[py];
        }
        sv[2*p]=s0; qv[2*p]=q0; sv[2*p+1]=s1; qv[2*p+1]=q1;
    }
    // reduce over the 8 pixel-slots in this warp (lanes differing in bits 2..4)
#pragma unroll
    for (int o=16; o>=4; o>>=1){
#pragma unroll
        for (int j=0;j<4;j++){
            sv[j] += __shfl_xor_sync(0xffffffffu, sv[j], o);
            qv[j] += __shfl_xor_sync(0xffffffffu, qv[j], o);
        }
    }
    if ((tid & 31) < 4){
        const int wd = tid >> 5;
#pragma unroll
        for (int j=0;j<4;j++){
            s_red[wd][cg][j]   = sv[j];
            s_red[wd][cg][4+j] = qv[j];
        }
    }
    __syncthreads();
    if (tid < 32){
        const bool isq = tid >= 16;
        const int co = tid & 15;
        const int cgg = co >> 2, j = co & 3;
        const int off = isq ? (4+j) : j;
        float t = s_red[0][cgg][off] + s_red[1][cgg][off]
                + s_red[2][cgg][off] + s_red[3][cgg][off];
        t *= tp.mult[osl];
        atomicAdd(isq ? &stat_q[co] : &stat_s[co], t);
    }
}

// ---------------- stats zero ----------------
__global__ void zero_stats(){
    int i = threadIdx.x;
    if (i < 64){ g_sum[i]=0.f; g_sumsq[i]=0.f; }
}

// ---------------- fused final elementwise + forward projection ----------------
// final[sl] = relu( norm3(s3[sl]) + relu( norm1(s2[skm[sl]]) + V ) )
// out[c,0,z,u] = weighted slice sum at (z,y=u)
// out[c,1,z,u] = column sum over y of slice sel(u); u==0 sums only y=0..63
//   (reference fp32: x=+-3.9e-15 at uu=0, valid mask kills y in [64,127]).
__global__ __launch_bounds__(128) void forward_proj(
    const float* __restrict__ s3, const float* __restrict__ s2,
    const float* __restrict__ V, float* __restrict__ out)
{
    __shared__ float red[9][4];
    __shared__ float rs[9];
    const int c = blockIdx.x >> 7, z = blockIdx.x & 127;
    const int u = threadIdx.x;
    const int   skm[9]  = {0,1,2,2,2,2,2,3,4};
    const float mult[9] = {1.f,1.f,1.f,1.f,120.f,1.f,1.f,1.f,1.f};

    // inline stats finalize: bank1 (A2 output) and bank3 (B2 output)
    double sd1 = (double)g_sum[16+c], qd1 = (double)g_sumsq[16+c];
    double me1 = sd1/2097152.0;
    double i1d = 1.0/sqrt(qd1/2097152.0 - me1*me1 + 1e-5);
    const float i1 = (float)i1d, b1c = (float)(-me1*i1d);
    double sd3 = (double)g_sum[48+c], qd3 = (double)g_sumsq[48+c];
    double me3 = sd3/2097152.0;
    double i3d = 1.0/sqrt(qd3/2097152.0 - me3*me3 + 1e-5);
    const float i3 = (float)i3d, b3c = (float)(-me3*i3d);

    const int pix = z*128 + u;
    const float vb = V[c*HW + pix];

    float vals[9]; float s0 = 0.f;
#pragma unroll
    for (int sdx=0; sdx<9; sdx++){
        float t2 = s2[(size_t)(skm[sdx]*16 + c)*HW + pix];
        float sk = fmaxf(fmaf(t2, i1, b1c) + vb, 0.f);
        float t3 = s3[(size_t)(sdx*16 + c)*HW + pix];
        float fv = fmaxf(fmaf(t3, i3, b3c) + sk, 0.f);
        vals[sdx] = fv;
        s0 += mult[sdx]*fv;
    }
    out[(c*2+0)*HW + pix] = s0;

    const int lane = u & 31, wid = u >> 5;
#pragma unroll
    for (int sdx=0; sdx<9; sdx++){
        float v = vals[sdx];
#pragma unroll
        for (int o=16;o>0;o>>=1) v += __shfl_xor_sync(0xffffffffu, v, o);
        if (lane==0) red[sdx][wid]=v;
    }
    __syncthreads();
    if (u < 9) rs[u] = red[u][0]+red[u][1]+red[u][2]+red[u][3];
    __syncthreads();
    const int sl = (u<4) ? u : (u>123 ? u-119 : 4);
    float o1 = (u==0) ? (red[0][0]+red[0][1]) : rs[sl];
    out[(c*2+1)*HW + pix] = o1;
}

// ---------------- launch ----------------
extern "C" void kernel_launch(void* const* d_in, const int* in_sizes, int n_in,
                              void* d_out, int out_size)
{
    (void)in_sizes; (void)n_in; (void)out_size;
    const float* V    = (const float*)d_in[0];
    const float* w_a1 = (const float*)d_in[1];
    const float* b_a1 = (const float*)d_in[2];
    const float* w_a2 = (const float*)d_in[3];
    const float* b_a2 = (const float*)d_in[4];
    const float* w_b1 = (const float*)d_in[5];
    const float* b_b1 = (const float*)d_in[6];
    const float* w_b2 = (const float*)d_in[7];
    const float* b_b2 = (const float*)d_in[8];
    float* out = (float*)d_out;

    float *b1,*b2,*b3,*gsum,*gsq;
    cudaGetSymbolAddress((void**)&b1,    g_b1);
    cudaGetSymbolAddress((void**)&b2,    g_b2);
    cudaGetSymbolAddress((void**)&b3,    g_b3);
    cudaGetSymbolAddress((void**)&gsum,  g_sum);
    cudaGetSymbolAddress((void**)&gsq,   g_sumsq);

    // merged tap tables: (input slice, kx bitmask) per output slice
    Taps tA1 = {
        { {0,-1,-1},{0,-1,-1},{0,-1,-1} },
        { {6,0,0},{7,0,0},{3,0,0} },
        { 1.f,126.f,1.f }
    };
    Taps tA2 = {
        { {0,1,-1},{0,1,-1},{1,-1,-1},{1,2,-1},{1,2,-1} },
        { {2,4,0},{1,6,0},{7,0,0},{3,4,0},{1,2,0} },
        { 1.f,1.f,124.f,1.f,1.f }
    };
    Taps tB1 = {
        { {0,1,-1},{0,1,2},{1,2,-1},{2,-1,-1},{2,3,-1},{2,3,4},{3,4,-1} },
        { {2,4,0},{1,2,4},{1,6,0},{7,0,0},{3,4,0},{1,2,4},{1,2,0} },
        { 1.f,1.f,1.f,122.f,1.f,1.f,1.f }
    };
    Taps tB2 = {
        { {0,1,-1},{0,1,2},{1,2,3},{2,3,-1},{3,-1,-1},{3,4,-1},{3,4,5},{4,5,6},{5,6,-1} },
        { {2,4,0},{1,2,4},{1,2,4},{1,6,0},{7,0,0},{3,4,0},{1,2,4},{1,2,4},{1,2,0} },
        { 1.f,1.f,1.f,1.f,120.f,1.f,1.f,1.f,1.f }
    };

    zero_stats<<<1,64>>>();

    // A1: raw V (slice stride 0) -> b1 (3 slices), stats bank 0
    conv_stage<0><<<dim3(128,3),128>>>(V, 0, b1, w_a1, b_a1,
                                       nullptr, nullptr, nullptr,
                                       gsum+0, gsq+0, tA1);

    // A2: norm_relu(b1, bank0) -> b2 (5), stats bank 1
    conv_stage<1><<<dim3(128,5),128>>>(b1, CHW, b2, w_a2, b_a2,
                                       gsum+0, gsq+0, nullptr,
                                       gsum+16, gsq+16, tA2);

    // B1: relu(norm(b2, bank1) + V) -> b1 (7), stats bank 2
    conv_stage<2><<<dim3(128,7),128>>>(b2, CHW, b1, w_b1, b_b1,
                                       gsum+16, gsq+16, V,
                                       gsum+32, gsq+32, tB1);

    // B2: norm_relu(b1, bank2) -> b3 (9), stats bank 3
    conv_stage<1><<<dim3(128,9),128>>>(b1, CHW, b3, w_b2, b_b2,
                                       gsum+32, gsq+32, nullptr,
                                       gsum+48, gsq+48, tB2);

    // fused final norm+skip+relu + both projections (bank1+bank3 inline)
    forward_proj<<<16*128,128>>>(b3, b2, V, out);
}

// round 10
// speedup vs baseline: 1.3755x; 1.0640x over previous
#include <cuda_runtime.h>
#include <math.h>

#define HW   (128*128)
#define CHW  (16*HW)
typedef unsigned long long ull;

// ---------------- scratch ----------------
__device__ float g_b1[7*CHW];    // conv1 out (3) / conv3 out (7)
__device__ float g_b2[5*CHW];    // conv2 out (5) -- kept for final skip recompute
__device__ float g_b3[9*CHW];    // conv4 out (9)
__device__ float g_sum[4*16];
__device__ float g_sumsq[4*16];

struct Taps { int isl[9][3]; int msk[9][3]; float mult[9]; };

// ---------------- f32x2 helpers ----------------
__device__ __forceinline__ ull pack2(float v){
    ull r; asm("mov.b64 %0,{%1,%2};" : "=l"(r) : "f"(v), "f"(v)); return r;
}
__device__ __forceinline__ void fma2(ull &d, ull a, ull b){
    asm("fma.rn.f32x2 %0,%1,%2,%0;" : "+l"(d) : "l"(a), "l"(b));
}
__device__ __forceinline__ void unpack2(ull a, float &x, float &y){
    asm("mov.b64 {%0,%1},%2;" : "=f"(x), "=f"(y) : "l"(a));
}

// ---------------- fused conv stage ----------------
// MODE 0: raw input. MODE 1: relu(fma(x,a,b)), a=istd, b=-mean*istd finalized
// inline from raw atomic sums. MODE 2: relu(fma(x,a,b) + skip).
// Halo: transform only in-range pixels; out-of-range pad = 0.
// Block: 128 threads = 32 pixel-slots x 4 co-groups. Thread = 1x4 px strip x
// 4 co (8 f32x2 accs). s_in rows padded to 20 floats so per-thread value
// reads are LDS.128/LDS.64 (6 LDS/ci instead of 18).
// Tile 8z x 16y; grid x = 128 tiles, y = output slice. 8 blocks/SM.
template<int MODE>
__global__ __launch_bounds__(128, 8) void conv_stage(
    const float* __restrict__ in, size_t in_stride,
    float* __restrict__ out,
    const float* __restrict__ w, const float* __restrict__ bias,
    const float* __restrict__ prev_s, const float* __restrict__ prev_q,
    const float* __restrict__ skip,
    float* __restrict__ stat_s, float* __restrict__ stat_q,
    Taps tp)
{
    __shared__ __align__(16) float s_w[16*9*16];   // [ci][k][co], mask-summed
    __shared__ __align__(16) float s_in[16*200];   // [ci][r(10)][c(20, 18 used)]
    __shared__ float s_a[16], s_b[16];
    __shared__ float s_red[4][4][8];    // [warp][cg][4 s + 4 q]

    const int osl = blockIdx.y;
    const int tile = blockIdx.x;
    const int tz0 = (tile >> 3) << 3;   // 16 z-tiles of 8
    const int ty0 = (tile &  7) << 4;   // 8 y-tiles of 16
    const int tid = threadIdx.x;
    const int cg   = tid & 3;           // co-group: co = cg*4 .. cg*4+3
    const int slot = tid >> 2;          // 0..31 pixel slot
    const int tz   = slot >> 2;         // 0..7
    const int tyq  = slot & 3;          // 0..3 -> y = tyq*4 .. tyq*4+3

    // inline finalize of previous stage's instance-norm stats
    if (MODE > 0 && tid < 16){
        double sd = (double)prev_s[tid];
        double qd = (double)prev_q[tid];
        double mean = sd / 2097152.0;
        double var  = qd / 2097152.0 - mean*mean;
        double isd  = 1.0 / sqrt(var + 1e-5);
        s_a[tid] = (float)isd;
        s_b[tid] = (float)(-mean*isd);
    }

    // tile-load slots over 180 logical entries (r=j/18, c=j%18):
    // slot0 = tid (<180 when tid<180 -> always for 128), slot1 = tid+128 (tid<52)
    int px0, px1, so0, so1; bool ok0, ok1;
    {
        int r = tid/18, c = tid - r*18;
        int gz = tz0 + r - 1, gy = ty0 + c - 1;
        ok0 = ((unsigned)gz < 128u) && ((unsigned)gy < 128u);
        px0 = gz*128 + gy;
        so0 = r*20 + c;
        int j = tid + 128;
        r = j/18; c = j - r*18;
        gz = tz0 + r - 1; gy = ty0 + c - 1;
        ok1 = (j < 180) && ((unsigned)gz < 128u) && ((unsigned)gy < 128u);
        px1 = gz*128 + gy;
        so1 = r*20 + c;
    }

    ull acc[2][4];                      // [co-pair][py]
#pragma unroll
    for (int p=0;p<2;p++)
#pragma unroll
    for (int py=0;py<4;py++) acc[p][py] = 0ull;

    for (int e=0; e<3; e++){
        const int isl = tp.isl[osl][e];
        if (isl < 0) continue;
        const int m = tp.msk[osl][e];
        __syncthreads();
        // weights (summed over kx taps sharing this input slice): 2304/128=18
#pragma unroll
        for (int it=0; it<18; it++){
            int idx = tid + it*128;
            int co = idx & 15;
            int k  = (idx >> 4) % 9;
            int ci = idx / 144;
            int base = ((co*16+ci)*9 + k)*3;
            float wv = 0.f;
            if (m & 1) wv += w[base+0];
            if (m & 2) wv += w[base+1];
            if (m & 4) wv += w[base+2];
            s_w[idx] = wv;
        }
        // input tile: ci batched in groups of 4 (MLP ~4-16)
        const float* ip = in + (size_t)isl*in_stride;
#pragma unroll
        for (int cgl=0; cgl<16; cgl+=4){
            float xv[4];
#pragma unroll
            for (int u2=0; u2<4; u2++)
                xv[u2] = ok0 ? ip[(cgl+u2)*HW + px0] : 0.f;
            if (MODE == 2){
                float svv[4];
#pragma unroll
                for (int u2=0; u2<4; u2++)
                    svv[u2] = ok0 ? skip[(cgl+u2)*HW + px0] : 0.f;
#pragma unroll
                for (int u2=0; u2<4; u2++){
                    float t = fmaxf(fmaf(xv[u2], s_a[cgl+u2], s_b[cgl+u2]) + svv[u2], 0.f);
                    s_in[(cgl+u2)*200 + so0] = ok0 ? t : 0.f;
                }
            } else if (MODE == 1){
#pragma unroll
                for (int u2=0; u2<4; u2++){
                    float t = fmaxf(fmaf(xv[u2], s_a[cgl+u2], s_b[cgl+u2]), 0.f);
                    s_in[(cgl+u2)*200 + so0] = ok0 ? t : 0.f;
                }
            } else {
#pragma unroll
                for (int u2=0; u2<4; u2++)
                    s_in[(cgl+u2)*200 + so0] = xv[u2];
            }
        }
        if (tid < 52){
#pragma unroll
            for (int cgl=0; cgl<16; cgl+=4){
                float xv[4];
#pragma unroll
                for (int u2=0; u2<4; u2++)
                    xv[u2] = ok1 ? ip[(cgl+u2)*HW + px1] : 0.f;
                if (MODE == 2){
                    float svv[4];
#pragma unroll
                    for (int u2=0; u2<4; u2++)
                        svv[u2] = ok1 ? skip[(cgl+u2)*HW + px1] : 0.f;
#pragma unroll
                    for (int u2=0; u2<4; u2++){
                        float t = fmaxf(fmaf(xv[u2], s_a[cgl+u2], s_b[cgl+u2]) + svv[u2], 0.f);
                        s_in[(cgl+u2)*200 + so1] = ok1 ? t : 0.f;
                    }
                } else if (MODE == 1){
#pragma unroll
                    for (int u2=0; u2<4; u2++){
                        float t = fmaxf(fmaf(xv[u2], s_a[cgl+u2], s_b[cgl+u2]), 0.f);
                        s_in[(cgl+u2)*200 + so1] = ok1 ? t : 0.f;
                    }
                } else {
#pragma unroll
                    for (int u2=0; u2<4; u2++)
                        s_in[(cgl+u2)*200 + so1] = xv[u2];
                }
            }
        }
        __syncthreads();

        // compute: 4 px x 4 co. Per (ci,kz): 1 LDS.128 + 1 LDS.64 values;
        // per (ci,k): 1 LDS.128 weights.
        const float* sbase = s_in + tz*20 + tyq*4;
        const float* wb    = s_w  + cg*4;
#pragma unroll 1
        for (int ci=0; ci<16; ci++){
            const float* si    = sbase + ci*200;
            const float* wbase = wb    + ci*144;
#pragma unroll
            for (int kz=0; kz<3; kz++){
                const float* row = si + kz*20;
                float4 va = *reinterpret_cast<const float4*>(row);
                float2 vb = *reinterpret_cast<const float2*>(row + 4);
                ull pv[6];
                pv[0]=pack2(va.x); pv[1]=pack2(va.y); pv[2]=pack2(va.z);
                pv[3]=pack2(va.w); pv[4]=pack2(vb.x); pv[5]=pack2(vb.y);
#pragma unroll
                for (int ky=0; ky<3; ky++){
                    ulonglong2 wq = *reinterpret_cast<const ulonglong2*>(wbase + (kz*3+ky)*16);
#pragma unroll
                    for (int py=0; py<4; py++){
                        fma2(acc[0][py], pv[ky+py], wq.x);
                        fma2(acc[1][py], pv[ky+py], wq.y);
                    }
                }
            }
        }
    }

    // epilogue: bias, vectorized store, fused stats
    const int oz  = tz0 + tz;
    const int oy0 = ty0 + tyq*4;
    float* op = out + (size_t)osl*CHW + oz*128 + oy0;

    float sv[4], qv[4];
#pragma unroll
    for (int p=0; p<2; p++){
        const int c0 = cg*4 + 2*p, c1 = c0 + 1;
        const float b0 = bias[c0], b1 = bias[c1];
        float r0[4], r1[4];
#pragma unroll
        for (int py=0; py<4; py++){
            float x,y; unpack2(acc[p][py], x, y);
            r0[py] = x + b0;
            r1[py] = y + b1;
        }
        *reinterpret_cast<float4*>(op + c0*HW) = make_float4(r0[0],r0[1],r0[2],r0[3]);
        *reinterpret_cast<float4*>(op + c1*HW) = make_float4(r1[0],r1[1],r1[2],r1[3]);
        float s0=0.f,q0=0.f,s1=0.f,q1=0.f;
#pragma unroll
        for (int py=0; py<4; py++){
            s0 += r0[py]; q0 += r0[py]*r0[py];
            s1 += r1[py]; q1 += r1[py]*r1[py];
        }
        sv[2*p]=s0; qv[2*p]=q0; sv[2*p+1]=s1; qv[2*p+1]=q1;
    }
    // reduce over the 8 pixel-slots in this warp (lanes differing in bits 2..4)
#pragma unroll
    for (int o=16; o>=4; o>>=1){
#pragma unroll
        for (int j=0;j<4;j++){
            sv[j] += __shfl_xor_sync(0xffffffffu, sv[j], o);
            qv[j] += __shfl_xor_sync(0xffffffffu, qv[j], o);
        }
    }
    if ((tid & 31) < 4){
        const int wd = tid >> 5;
#pragma unroll
        for (int j=0;j<4;j++){
            s_red[wd][cg][j]   = sv[j];
            s_red[wd][cg][4+j] = qv[j];
        }
    }
    __syncthreads();
    if (tid < 32){
        const bool isq = tid >= 16;
        const int co = tid & 15;
        const int cgg = co >> 2, j = co & 3;
        const int off = isq ? (4+j) : j;
        float t = s_red[0][cgg][off] + s_red[1][cgg][off]
                + s_red[2][cgg][off] + s_red[3][cgg][off];
        t *= tp.mult[osl];
        atomicAdd(isq ? &stat_q[co] : &stat_s[co], t);
    }
}

// ---------------- stats zero ----------------
__global__ void zero_stats(){
    int i = threadIdx.x;
    if (i < 64){ g_sum[i]=0.f; g_sumsq[i]=0.f; }
}

// ---------------- fused final elementwise + forward projection ----------------
// final[sl] = relu( norm3(s3[sl]) + relu( norm1(s2[skm[sl]]) + V ) )
// out[c,0,z,u] = weighted slice sum at (z,y=u)
// out[c,1,z,u] = column sum over y of slice sel(u); u==0 sums only y=0..63
//   (reference fp32: x=+-3.9e-15 at uu=0, valid mask kills y in [64,127]).
__global__ __launch_bounds__(128) void forward_proj(
    const float* __restrict__ s3, const float* __restrict__ s2,
    const float* __restrict__ V, float* __restrict__ out)
{
    __shared__ float red[9][4];
    __shared__ float rs[9];
    const int c = blockIdx.x >> 7, z = blockIdx.x & 127;
    const int u = threadIdx.x;
    const int   skm[9]  = {0,1,2,2,2,2,2,3,4};
    const float mult[9] = {1.f,1.f,1.f,1.f,120.f,1.f,1.f,1.f,1.f};

    // inline stats finalize: bank1 (A2 output) and bank3 (B2 output)
    double sd1 = (double)g_sum[16+c], qd1 = (double)g_sumsq[16+c];
    double me1 = sd1/2097152.0;
    double i1d = 1.0/sqrt(qd1/2097152.0 - me1*me1 + 1e-5);
    const float i1 = (float)i1d, b1c = (float)(-me1*i1d);
    double sd3 = (double)g_sum[48+c], qd3 = (double)g_sumsq[48+c];
    double me3 = sd3/2097152.0;
    double i3d = 1.0/sqrt(qd3/2097152.0 - me3*me3 + 1e-5);
    const float i3 = (float)i3d, b3c = (float)(-me3*i3d);

    const int pix = z*128 + u;
    const float vb = V[c*HW + pix];

    float vals[9]; float s0 = 0.f;
#pragma unroll
    for (int sdx=0; sdx<9; sdx++){
        float t2 = s2[(size_t)(skm[sdx]*16 + c)*HW + pix];
        float sk = fmaxf(fmaf(t2, i1, b1c) + vb, 0.f);
        float t3 = s3[(size_t)(sdx*16 + c)*HW + pix];
        float fv = fmaxf(fmaf(t3, i3, b3c) + sk, 0.f);
        vals[sdx] = fv;
        s0 += mult[sdx]*fv;
    }
    out[(c*2+0)*HW + pix] = s0;

    const int lane = u & 31, wid = u >> 5;
#pragma unroll
    for (int sdx=0; sdx<9; sdx++){
        float v = vals[sdx];
#pragma unroll
        for (int o=16;o>0;o>>=1) v += __shfl_xor_sync(0xffffffffu, v, o);
        if (lane==0) red[sdx][wid]=v;
    }
    __syncthreads();
    if (u < 9) rs[u] = red[u][0]+red[u][1]+red[u][2]+red[u][3];
    __syncthreads();
    const int sl = (u<4) ? u : (u>123 ? u-119 : 4);
    float o1 = (u==0) ? (red[0][0]+red[0][1]) : rs[sl];
    out[(c*2+1)*HW + pix] = o1;
}

// ---------------- launch ----------------
extern "C" void kernel_launch(void* const* d_in, const int* in_sizes, int n_in,
                              void* d_out, int out_size)
{
    (void)in_sizes; (void)n_in; (void)out_size;
    const float* V    = (const float*)d_in[0];
    const float* w_a1 = (const float*)d_in[1];
    const float* b_a1 = (const float*)d_in[2];
    const float* w_a2 = (const float*)d_in[3];
    const float* b_a2 = (const float*)d_in[4];
    const float* w_b1 = (const float*)d_in[5];
    const float* b_b1 = (const float*)d_in[6];
    const float* w_b2 = (const float*)d_in[7];
    const float* b_b2 = (const float*)d_in[8];
    float* out = (float*)d_out;

    float *b1,*b2,*b3,*gsum,*gsq;
    cudaGetSymbolAddress((void**)&b1,    g_b1);
    cudaGetSymbolAddress((void**)&b2,    g_b2);
    cudaGetSymbolAddress((void**)&b3,    g_b3);
    cudaGetSymbolAddress((void**)&gsum,  g_sum);
    cudaGetSymbolAddress((void**)&gsq,   g_sumsq);

    // merged tap tables: (input slice, kx bitmask) per output slice
    Taps tA1 = {
        { {0,-1,-1},{0,-1,-1},{0,-1,-1} },
        { {6,0,0},{7,0,0},{3,0,0} },
        { 1.f,126.f,1.f }
    };
    Taps tA2 = {
        { {0,1,-1},{0,1,-1},{1,-1,-1},{1,2,-1},{1,2,-1} },
        { {2,4,0},{1,6,0},{7,0,0},{3,4,0},{1,2,0} },
        { 1.f,1.f,124.f,1.f,1.f }
    };
    Taps tB1 = {
        { {0,1,-1},{0,1,2},{1,2,-1},{2,-1,-1},{2,3,-1},{2,3,4},{3,4,-1} },
        { {2,4,0},{1,2,4},{1,6,0},{7,0,0},{3,4,0},{1,2,4},{1,2,0} },
        { 1.f,1.f,1.f,122.f,1.f,1.f,1.f }
    };
    Taps tB2 = {
        { {0,1,-1},{0,1,2},{1,2,3},{2,3,-1},{3,-1,-1},{3,4,-1},{3,4,5},{4,5,6},{5,6,-1} },
        { {2,4,0},{1,2,4},{1,2,4},{1,6,0},{7,0,0},{3,4,0},{1,2,4},{1,2,4},{1,2,0} },
        { 1.f,1.f,1.f,1.f,120.f,1.f,1.f,1.f,1.f }
    };

    zero_stats<<<1,64>>>();

    // A1: raw V (slice stride 0) -> b1 (3 slices), stats bank 0
    conv_stage<0><<<dim3(128,3),128>>>(V, 0, b1, w_a1, b_a1,
                                       nullptr, nullptr, nullptr,
                                       gsum+0, gsq+0, tA1);

    // A2: norm_relu(b1, bank0) -> b2 (5), stats bank 1
    conv_stage<1><<<dim3(128,5),128>>>(b1, CHW, b2, w_a2, b_a2,
                                       gsum+0, gsq+0, nullptr,
                                       gsum+16, gsq+16, tA2);

    // B1: relu(norm(b2, bank1) + V) -> b1 (7), stats bank 2
    conv_stage<2><<<dim3(128,7),128>>>(b2, CHW, b1, w_b1, b_b1,
                                       gsum+16, gsq+16, V,
                                       gsum+32, gsq+32, tB1);

    // B2: norm_relu(b1, bank2) -> b3 (9), stats bank 3
    conv_stage<1><<<dim3(128,9),128>>>(b1, CHW, b3, w_b2, b_b2,
                                       gsum+32, gsq+32, nullptr,
                                       gsum+48, gsq+48, tB2);

    // fused final norm+skip+relu + both projections (bank1+bank3 inline)
    forward_proj<<<16*128,128>>>(b3, b2, V, out);
}

// round 11
// speedup vs baseline: 1.6987x; 1.2349x over previous
#include <cuda_runtime.h>
#include <math.h>

#define HW   (128*128)
#define CHW  (16*HW)
#define WSTG (9*3*2304)      // merged-weight floats per stage
typedef unsigned long long ull;

// ---------------- scratch ----------------
__device__ float g_b1[7*CHW];    // conv1 out (3) / conv3 out (7)
__device__ float g_b2[5*CHW];    // conv2 out (5) -- kept for final skip recompute
__device__ float g_b3[9*CHW];    // conv4 out (9)
__device__ float g_wm[4*WSTG];   // pre-merged weights [stage][osl][e][ci*144+k*16+co]
__device__ float g_sum[4*16];
__device__ float g_sumsq[4*16];

struct Taps { int isl[9][3]; int msk[9][3]; float mult[9]; };
struct MergeArgs { const float* w[4]; Taps tp[4]; int n_osl[4]; };

// ---------------- f32x2 helpers ----------------
__device__ __forceinline__ ull pack2(float v){
    ull r; asm("mov.b64 %0,{%1,%2};" : "=l"(r) : "f"(v), "f"(v)); return r;
}
__device__ __forceinline__ void fma2(ull &d, ull a, ull b){
    asm("fma.rn.f32x2 %0,%1,%2,%0;" : "+l"(d) : "l"(a), "l"(b));
}
__device__ __forceinline__ void unpack2(ull a, float &x, float &y){
    asm("mov.b64 {%0,%1},%2;" : "=f"(x), "=f"(y) : "l"(a));
}

// ---------------- setup: merge weights (once) + zero stats ----------------
// grid (3, 9, 4): x=e, y=osl, z=stage. Scattered reads happen ONCE here
// instead of per spatial tile inside the conv stages.
__global__ __launch_bounds__(128) void merge_weights(MergeArgs a)
{
    const int e = blockIdx.x, osl = blockIdx.y, st = blockIdx.z;
    const int tid = threadIdx.x;
    if (e==0 && osl==0 && st==0 && tid < 64){ g_sum[tid]=0.f; g_sumsq[tid]=0.f; }
    if (osl >= a.n_osl[st]) return;
    const int isl = a.tp[st].isl[osl][e];
    if (isl < 0) return;
    const int m = a.tp[st].msk[osl][e];
    const float* w = a.w[st];
    float* dst = g_wm + st*WSTG + (osl*3 + e)*2304;
#pragma unroll
    for (int it=0; it<18; it++){
        int idx = tid + it*128;
        int co = idx & 15;
        int k  = (idx >> 4) % 9;
        int ci = idx / 144;
        int base = ((co*16+ci)*9 + k)*3;
        float wv = 0.f;
        if (m & 1) wv += w[base+0];
        if (m & 2) wv += w[base+1];
        if (m & 4) wv += w[base+2];
        dst[idx] = wv;
    }
}

// ---------------- fused conv stage ----------------
// MODE 0: raw input. MODE 1: relu(fma(x,a,b)), a=istd, b=-mean*istd finalized
// inline from raw atomic sums. MODE 2: relu(fma(x,a,b) + skip).
// Halo: transform only in-range pixels; out-of-range pad = 0.
// Block: 128 threads = 32 pixel-slots x 4 co-groups. Thread = 1x4 px strip x
// 4 co (8 f32x2 accs). s_in rows padded to 20 floats (LDS.128/.64 values).
// Weights pre-merged in g_wm; pass fill = coalesced float4 copy.
// Tile 8z x 16y; grid x = 128 tiles, y = output slice. ~6 blocks/SM.
template<int MODE>
__global__ __launch_bounds__(128, 6) void conv_stage(
    const float* __restrict__ in, size_t in_stride,
    float* __restrict__ out,
    const float* __restrict__ wm, const float* __restrict__ bias,
    const float* __restrict__ prev_s, const float* __restrict__ prev_q,
    const float* __restrict__ skip,
    float* __restrict__ stat_s, float* __restrict__ stat_q,
    Taps tp)
{
    __shared__ __align__(16) float s_w[16*9*16];   // [ci][k][co]
    __shared__ __align__(16) float s_in[16*200];   // [ci][r(10)][c(20, 18 used)]
    __shared__ float s_a[16], s_b[16];
    __shared__ float s_red[4][4][8];    // [warp][cg][4 s + 4 q]

    const int osl = blockIdx.y;
    const int tile = blockIdx.x;
    const int tz0 = (tile >> 3) << 3;   // 16 z-tiles of 8
    const int ty0 = (tile &  7) << 4;   // 8 y-tiles of 16
    const int tid = threadIdx.x;
    const int cg   = tid & 3;           // co-group: co = cg*4 .. cg*4+3
    const int slot = tid >> 2;          // 0..31 pixel slot
    const int tz   = slot >> 2;         // 0..7
    const int tyq  = slot & 3;          // 0..3 -> y = tyq*4 .. tyq*4+3

    // inline finalize of previous stage's instance-norm stats
    if (MODE > 0 && tid < 16){
        double sd = (double)prev_s[tid];
        double qd = (double)prev_q[tid];
        double mean = sd / 2097152.0;
        double var  = qd / 2097152.0 - mean*mean;
        double isd  = 1.0 / sqrt(var + 1e-5);
        s_a[tid] = (float)isd;
        s_b[tid] = (float)(-mean*isd);
    }

    // tile-load slots over 180 logical entries (r=j/18, c=j%18)
    int px0, px1, so0, so1; bool ok0, ok1;
    {
        int r = tid/18, c = tid - r*18;
        int gz = tz0 + r - 1, gy = ty0 + c - 1;
        ok0 = ((unsigned)gz < 128u) && ((unsigned)gy < 128u);
        px0 = gz*128 + gy;
        so0 = r*20 + c;
        int j = tid + 128;
        r = j/18; c = j - r*18;
        gz = tz0 + r - 1; gy = ty0 + c - 1;
        ok1 = (j < 180) && ((unsigned)gz < 128u) && ((unsigned)gy < 128u);
        px1 = gz*128 + gy;
        so1 = r*20 + c;
    }

    ull acc[2][4];                      // [co-pair][py]
#pragma unroll
    for (int p=0;p<2;p++)
#pragma unroll
    for (int py=0;py<4;py++) acc[p][py] = 0ull;

    for (int e=0; e<3; e++){
        const int isl = tp.isl[osl][e];
        if (isl < 0) continue;
        __syncthreads();
        // weights: coalesced copy of pre-merged slab (576 float4)
        {
            const float4* wmp = reinterpret_cast<const float4*>(wm + (osl*3 + e)*2304);
            float4* swp = reinterpret_cast<float4*>(s_w);
#pragma unroll
            for (int it=0; it<4; it++)
                swp[tid + it*128] = wmp[tid + it*128];
            if (tid < 64) swp[tid + 512] = wmp[tid + 512];
        }
        // input tile: ci batched in groups of 4 (MLP ~4-16)
        const float* ip = in + (size_t)isl*in_stride;
#pragma unroll
        for (int cgl=0; cgl<16; cgl+=4){
            float xv[4];
#pragma unroll
            for (int u2=0; u2<4; u2++)
                xv[u2] = ok0 ? ip[(cgl+u2)*HW + px0] : 0.f;
            if (MODE == 2){
                float svv[4];
#pragma unroll
                for (int u2=0; u2<4; u2++)
                    svv[u2] = ok0 ? skip[(cgl+u2)*HW + px0] : 0.f;
#pragma unroll
                for (int u2=0; u2<4; u2++){
                    float t = fmaxf(fmaf(xv[u2], s_a[cgl+u2], s_b[cgl+u2]) + svv[u2], 0.f);
                    s_in[(cgl+u2)*200 + so0] = ok0 ? t : 0.f;
                }
            } else if (MODE == 1){
#pragma unroll
                for (int u2=0; u2<4; u2++){
                    float t = fmaxf(fmaf(xv[u2], s_a[cgl+u2], s_b[cgl+u2]), 0.f);
                    s_in[(cgl+u2)*200 + so0] = ok0 ? t : 0.f;
                }
            } else {
#pragma unroll
                for (int u2=0; u2<4; u2++)
                    s_in[(cgl+u2)*200 + so0] = xv[u2];
            }
        }
        if (tid < 52){
#pragma unroll
            for (int cgl=0; cgl<16; cgl+=4){
                float xv[4];
#pragma unroll
                for (int u2=0; u2<4; u2++)
                    xv[u2] = ok1 ? ip[(cgl+u2)*HW + px1] : 0.f;
                if (MODE == 2){
                    float svv[4];
#pragma unroll
                    for (int u2=0; u2<4; u2++)
                        svv[u2] = ok1 ? skip[(cgl+u2)*HW + px1] : 0.f;
#pragma unroll
                    for (int u2=0; u2<4; u2++){
                        float t = fmaxf(fmaf(xv[u2], s_a[cgl+u2], s_b[cgl+u2]) + svv[u2], 0.f);
                        s_in[(cgl+u2)*200 + so1] = ok1 ? t : 0.f;
                    }
                } else if (MODE == 1){
#pragma unroll
                    for (int u2=0; u2<4; u2++){
                        float t = fmaxf(fmaf(xv[u2], s_a[cgl+u2], s_b[cgl+u2]), 0.f);
                        s_in[(cgl+u2)*200 + so1] = ok1 ? t : 0.f;
                    }
                } else {
#pragma unroll
                    for (int u2=0; u2<4; u2++)
                        s_in[(cgl+u2)*200 + so1] = xv[u2];
                }
            }
        }
        __syncthreads();

        // compute: 4 px x 4 co; unroll 2 over ci for latency pipelining
        const float* sbase = s_in + tz*20 + tyq*4;
        const float* wb    = s_w  + cg*4;
#pragma unroll 2
        for (int ci=0; ci<16; ci++){
            const float* si    = sbase + ci*200;
            const float* wbase = wb    + ci*144;
#pragma unroll
            for (int kz=0; kz<3; kz++){
                const float* row = si + kz*20;
                float4 va = *reinterpret_cast<const float4*>(row);
                float2 vb = *reinterpret_cast<const float2*>(row + 4);
                ull pv[6];
                pv[0]=pack2(va.x); pv[1]=pack2(va.y); pv[2]=pack2(va.z);
                pv[3]=pack2(va.w); pv[4]=pack2(vb.x); pv[5]=pack2(vb.y);
#pragma unroll
                for (int ky=0; ky<3; ky++){
                    ulonglong2 wq = *reinterpret_cast<const ulonglong2*>(wbase + (kz*3+ky)*16);
#pragma unroll
                    for (int py=0; py<4; py++){
                        fma2(acc[0][py], pv[ky+py], wq.x);
                        fma2(acc[1][py], pv[ky+py], wq.y);
                    }
                }
            }
        }
    }

    // epilogue: bias, vectorized store, fused stats
    const int oz  = tz0 + tz;
    const int oy0 = ty0 + tyq*4;
    float* op = out + (size_t)osl*CHW + oz*128 + oy0;

    float sv[4], qv[4];
#pragma unroll
    for (int p=0; p<2; p++){
        const int c0 = cg*4 + 2*p, c1 = c0 + 1;
        const float b0 = bias[c0], b1 = bias[c1];
        float r0[4], r1[4];
#pragma unroll
        for (int py=0; py<4; py++){
            float x,y; unpack2(acc[p][py], x, y);
            r0[py] = x + b0;
            r1[py] = y + b1;
        }
        *reinterpret_cast<float4*>(op + c0*HW) = make_float4(r0[0],r0[1],r0[2],r0[3]);
        *reinterpret_cast<float4*>(op + c1*HW) = make_float4(r1[0],r1[1],r1[2],r1[3]);
        float s0=0.f,q0=0.f,s1=0.f,q1=0.f;
#pragma unroll
        for (int py=0; py<4; py++){
            s0 += r0[py]; q0 += r0[py]*r0[py];
            s1 += r1[py]; q1 += r1[py]*r1[py];
        }
        sv[2*p]=s0; qv[2*p]=q0; sv[2*p+1]=s1; qv[2*p+1]=q1;
    }
#pragma unroll
    for (int o=16; o>=4; o>>=1){
#pragma unroll
        for (int j=0;j<4;j++){
            sv[j] += __shfl_xor_sync(0xffffffffu, sv[j], o);
            qv[j] += __shfl_xor_sync(0xffffffffu, qv[j], o);
        }
    }
    if ((tid & 31) < 4){
        const int wd = tid >> 5;
#pragma unroll
        for (int j=0;j<4;j++){
            s_red[wd][cg][j]   = sv[j];
            s_red[wd][cg][4+j] = qv[j];
        }
    }
    __syncthreads();
    if (tid < 32){
        const bool isq = tid >= 16;
        const int co = tid & 15;
        const int cgg = co >> 2, j = co & 3;
        const int off = isq ? (4+j) : j;
        float t = s_red[0][cgg][off] + s_red[1][cgg][off]
                + s_red[2][cgg][off] + s_red[3][cgg][off];
        t *= tp.mult[osl];
        atomicAdd(isq ? &stat_q[co] : &stat_s[co], t);
    }
}

// ---------------- fused final elementwise + forward projection ----------------
// final[sl] = relu( norm3(s3[sl]) + relu( norm1(s2[skm[sl]]) + V ) )
// out[c,0,z,u] = weighted slice sum at (z,y=u)
// out[c,1,z,u] = column sum over y of slice sel(u); u==0 sums only y=0..63
//   (reference fp32: x=+-3.9e-15 at uu=0, valid mask kills y in [64,127]).
__global__ __launch_bounds__(128) void forward_proj(
    const float* __restrict__ s3, const float* __restrict__ s2,
    const float* __restrict__ V, float* __restrict__ out)
{
    __shared__ float red[9][4];
    __shared__ float rs[9];
    const int c = blockIdx.x >> 7, z = blockIdx.x & 127;
    const int u = threadIdx.x;
    const int   skm[9]  = {0,1,2,2,2,2,2,3,4};
    const float mult[9] = {1.f,1.f,1.f,1.f,120.f,1.f,1.f,1.f,1.f};

    // inline stats finalize: bank1 (A2 output) and bank3 (B2 output)
    double sd1 = (double)g_sum[16+c], qd1 = (double)g_sumsq[16+c];
    double me1 = sd1/2097152.0;
    double i1d = 1.0/sqrt(qd1/2097152.0 - me1*me1 + 1e-5);
    const float i1 = (float)i1d, b1c = (float)(-me1*i1d);
    double sd3 = (double)g_sum[48+c], qd3 = (double)g_sumsq[48+c];
    double me3 = sd3/2097152.0;
    double i3d = 1.0/sqrt(qd3/2097152.0 - me3*me3 + 1e-5);
    const float i3 = (float)i3d, b3c = (float)(-me3*i3d);

    const int pix = z*128 + u;
    const float vb = V[c*HW + pix];

    float vals[9]; float s0 = 0.f;
#pragma unroll
    for (int sdx=0; sdx<9; sdx++){
        float t2 = s2[(size_t)(skm[sdx]*16 + c)*HW + pix];
        float sk = fmaxf(fmaf(t2, i1, b1c) + vb, 0.f);
        float t3 = s3[(size_t)(sdx*16 + c)*HW + pix];
        float fv = fmaxf(fmaf(t3, i3, b3c) + sk, 0.f);
        vals[sdx] = fv;
        s0 += mult[sdx]*fv;
    }
    out[(c*2+0)*HW + pix] = s0;

    const int lane = u & 31, wid = u >> 5;
#pragma unroll
    for (int sdx=0; sdx<9; sdx++){
        float v = vals[sdx];
#pragma unroll
        for (int o=16;o>0;o>>=1) v += __shfl_xor_sync(0xffffffffu, v, o);
        if (lane==0) red[sdx][wid]=v;
    }
    __syncthreads();
    if (u < 9) rs[u] = red[u][0]+red[u][1]+red[u][2]+red[u][3];
    __syncthreads();
    const int sl = (u<4) ? u : (u>123 ? u-119 : 4);
    float o1 = (u==0) ? (red[0][0]+red[0][1]) : rs[sl];
    out[(c*2+1)*HW + pix] = o1;
}

// ---------------- launch ----------------
extern "C" void kernel_launch(void* const* d_in, const int* in_sizes, int n_in,
                              void* d_out, int out_size)
{
    (void)in_sizes; (void)n_in; (void)out_size;
    const float* V    = (const float*)d_in[0];
    const float* w_a1 = (const float*)d_in[1];
    const float* b_a1 = (const float*)d_in[2];
    const float* w_a2 = (const float*)d_in[3];
    const float* b_a2 = (const float*)d_in[4];
    const float* w_b1 = (const float*)d_in[5];
    const float* b_b1 = (const float*)d_in[6];
    const float* w_b2 = (const float*)d_in[7];
    const float* b_b2 = (const float*)d_in[8];
    float* out = (float*)d_out;

    float *b1,*b2,*b3,*gsum,*gsq,*gwm;
    cudaGetSymbolAddress((void**)&b1,    g_b1);
    cudaGetSymbolAddress((void**)&b2,    g_b2);
    cudaGetSymbolAddress((void**)&b3,    g_b3);
    cudaGetSymbolAddress((void**)&gsum,  g_sum);
    cudaGetSymbolAddress((void**)&gsq,   g_sumsq);
    cudaGetSymbolAddress((void**)&gwm,   g_wm);

    // merged tap tables: (input slice, kx bitmask) per output slice
    Taps tA1 = {
        { {0,-1,-1},{0,-1,-1},{0,-1,-1} },
        { {6,0,0},{7,0,0},{3,0,0} },
        { 1.f,126.f,1.f }
    };
    Taps tA2 = {
        { {0,1,-1},{0,1,-1},{1,-1,-1},{1,2,-1},{1,2,-1} },
        { {2,4,0},{1,6,0},{7,0,0},{3,4,0},{1,2,0} },
        { 1.f,1.f,124.f,1.f,1.f }
    };
    Taps tB1 = {
        { {0,1,-1},{0,1,2},{1,2,-1},{2,-1,-1},{2,3,-1},{2,3,4},{3,4,-1} },
        { {2,4,0},{1,2,4},{1,6,0},{7,0,0},{3,4,0},{1,2,4},{1,2,0} },
        { 1.f,1.f,1.f,122.f,1.f,1.f,1.f }
    };
    Taps tB2 = {
        { {0,1,-1},{0,1,2},{1,2,3},{2,3,-1},{3,-1,-1},{3,4,-1},{3,4,5},{4,5,6},{5,6,-1} },
        { {2,4,0},{1,2,4},{1,2,4},{1,6,0},{7,0,0},{3,4,0},{1,2,4},{1,2,4},{1,2,0} },
        { 1.f,1.f,1.f,1.f,120.f,1.f,1.f,1.f,1.f }
    };

    MergeArgs ma;
    ma.w[0]=w_a1; ma.w[1]=w_a2; ma.w[2]=w_b1; ma.w[3]=w_b2;
    ma.tp[0]=tA1; ma.tp[1]=tA2; ma.tp[2]=tB1; ma.tp[3]=tB2;
    ma.n_osl[0]=3; ma.n_osl[1]=5; ma.n_osl[2]=7; ma.n_osl[3]=9;

    // setup: merge weights for all 4 stages + zero stats
    merge_weights<<<dim3(3,9,4),128>>>(ma);

    // A1: raw V (slice stride 0) -> b1 (3 slices), stats bank 0
    conv_stage<0><<<dim3(128,3),128>>>(V, 0, b1, gwm+0*WSTG, b_a1,
                                       nullptr, nullptr, nullptr,
                                       gsum+0, gsq+0, tA1);

    // A2: norm_relu(b1, bank0) -> b2 (5), stats bank 1
    conv_stage<1><<<dim3(128,5),128>>>(b1, CHW, b2, gwm+1*WSTG, b_a2,
                                       gsum+0, gsq+0, nullptr,
                                       gsum+16, gsq+16, tA2);

    // B1: relu(norm(b2, bank1) + V) -> b1 (7), stats bank 2
    conv_stage<2><<<dim3(128,7),128>>>(b2, CHW, b1, gwm+2*WSTG, b_b1,
                                       gsum+16, gsq+16, V,
                                       gsum+32, gsq+32, tB1);

    // B2: norm_relu(b1, bank2) -> b3 (9), stats bank 3
    conv_stage<1><<<dim3(128,9),128>>>(b1, CHW, b3, gwm+3*WSTG, b_b2,
                                       gsum+32, gsq+32, nullptr,
                                       gsum+48, gsq+48, tB2);

    // fused final norm+skip+relu + both projections (bank1+bank3 inline)
    forward_proj<<<16*128,128>>>(b3, b2, V, out);
}

// round 12
// speedup vs baseline: 1.7745x; 1.0447x over previous
#include <cuda_runtime.h>
#include <math.h>

#define HW   (128*128)
#define CHW  (16*HW)
#define WSTG (9*3*2304)      // merged-weight floats per stage
typedef unsigned long long ull;

// ---------------- scratch ----------------
__device__ float g_b1[7*CHW];    // conv1 out (3) / conv3 out (7)
__device__ float g_b2[5*CHW];    // conv2 out (5) -- kept for final skip recompute
__device__ float g_b3[9*CHW];    // conv4 out (9)
__device__ float g_wm[4*WSTG];   // pre-merged weights [stage][osl][e][ci*144+k*16+co]
__device__ float g_sum[4*16];
__device__ float g_sumsq[4*16];

struct Taps { int isl[9][3]; int msk[9][3]; float mult[9]; };
struct MergeArgs { const float* w[4]; Taps tp[4]; int n_osl[4]; };

// ---------------- f32x2 helpers ----------------
__device__ __forceinline__ ull pack2(float v){
    ull r; asm("mov.b64 %0,{%1,%2};" : "=l"(r) : "f"(v), "f"(v)); return r;
}
__device__ __forceinline__ void fma2(ull &d, ull a, ull b){
    asm("fma.rn.f32x2 %0,%1,%2,%0;" : "+l"(d) : "l"(a), "l"(b));
}
__device__ __forceinline__ void unpack2(ull a, float &x, float &y){
    asm("mov.b64 {%0,%1},%2;" : "=f"(x), "=f"(y) : "l"(a));
}

// ---------------- setup: merge weights (once) + zero stats ----------------
__global__ __launch_bounds__(128) void merge_weights(MergeArgs a)
{
    const int e = blockIdx.x, osl = blockIdx.y, st = blockIdx.z;
    const int tid = threadIdx.x;
    if (e==0 && osl==0 && st==0 && tid < 64){ g_sum[tid]=0.f; g_sumsq[tid]=0.f; }
    if (osl >= a.n_osl[st]) return;
    const int isl = a.tp[st].isl[osl][e];
    if (isl < 0) return;
    const int m = a.tp[st].msk[osl][e];
    const float* w = a.w[st];
    float* dst = g_wm + st*WSTG + (osl*3 + e)*2304;
#pragma unroll
    for (int it=0; it<18; it++){
        int idx = tid + it*128;
        int co = idx & 15;
        int k  = (idx >> 4) % 9;
        int ci = idx / 144;
        int base = ((co*16+ci)*9 + k)*3;
        float wv = 0.f;
        if (m & 1) wv += w[base+0];
        if (m & 2) wv += w[base+1];
        if (m & 4) wv += w[base+2];
        dst[idx] = wv;
    }
}

// ---------------- fused conv stage ----------------
// MODE 0: raw input. MODE 1: relu(fma(x,a,b)), a=istd, b=-mean*istd finalized
// inline from raw atomic sums. MODE 2: relu(fma(x,a,b) + skip).
// Halo: transform only in-range pixels; out-of-range pad = 0.
// Block: 128 threads = 32 strips x 4 co-groups. Thread = 1x8 px strip x 4 co
// (16 f32x2 accs). Weight LDS amortized over 8 px (was 4) -> L1 wavefronts
// drop below the fma-pipe floor. s_in rows padded to 36 floats for alignment.
// Tile 8z x 32y; grid x = 64 tiles, y = output slice.
template<int MODE>
__global__ __launch_bounds__(128, 4) void conv_stage(
    const float* __restrict__ in, size_t in_stride,
    float* __restrict__ out,
    const float* __restrict__ wm, const float* __restrict__ bias,
    const float* __restrict__ prev_s, const float* __restrict__ prev_q,
    const float* __restrict__ skip,
    float* __restrict__ stat_s, float* __restrict__ stat_q,
    Taps tp)
{
    __shared__ __align__(16) float s_w[16*9*16];   // [ci][k][co]
    __shared__ __align__(16) float s_in[16*360];   // [ci][r(10)][c(36, 34 used)]
    __shared__ float s_a[16], s_b[16];
    __shared__ float s_red[4][4][8];    // [warp][cg][4 s + 4 q]

    const int osl = blockIdx.y;
    const int tile = blockIdx.x;
    const int tz0 = (tile >> 2) << 3;   // 16 z-tiles of 8
    const int ty0 = (tile &  3) << 5;   // 4 y-tiles of 32
    const int tid = threadIdx.x;
    const int cg    = tid & 3;          // co-group: co = cg*4 .. cg*4+3
    const int slot  = tid >> 2;         // 0..31
    const int tz    = slot >> 2;        // 0..7
    const int strip = slot & 3;         // 0..3 -> y = strip*8 .. strip*8+7

    // inline finalize of previous stage's instance-norm stats
    if (MODE > 0 && tid < 16){
        double sd = (double)prev_s[tid];
        double qd = (double)prev_q[tid];
        double mean = sd / 2097152.0;
        double var  = qd / 2097152.0 - mean*mean;
        double isd  = 1.0 / sqrt(var + 1e-5);
        s_a[tid] = (float)isd;
        s_b[tid] = (float)(-mean*isd);
    }

    // tile-load slots over 340 logical entries (r=j/34, c=j%34)
    int pxs[3], sos[3]; bool oks[3];
#pragma unroll
    for (int s3=0; s3<3; s3++){
        int j = tid + s3*128;
        int r = j/34, c = j - r*34;
        int gz = tz0 + r - 1, gy = ty0 + c - 1;
        oks[s3] = (j < 340) && ((unsigned)gz < 128u) && ((unsigned)gy < 128u);
        pxs[s3] = gz*128 + gy;
        sos[s3] = r*36 + c;
    }
    const bool has2 = tid < 84;

    ull acc[2][8];                      // [co-pair][py]
#pragma unroll
    for (int p=0;p<2;p++)
#pragma unroll
    for (int py=0;py<8;py++) acc[p][py] = 0ull;

    for (int e=0; e<3; e++){
        const int isl = tp.isl[osl][e];
        if (isl < 0) continue;
        __syncthreads();
        // weights: coalesced copy of pre-merged slab (576 float4)
        {
            const float4* wmp = reinterpret_cast<const float4*>(wm + (osl*3 + e)*2304);
            float4* swp = reinterpret_cast<float4*>(s_w);
#pragma unroll
            for (int it=0; it<4; it++)
                swp[tid + it*128] = wmp[tid + it*128];
            if (tid < 64) swp[tid + 512] = wmp[tid + 512];
        }
        // input tile: ci batched in groups of 4, 3 slots per thread
        const float* ip = in + (size_t)isl*in_stride;
#pragma unroll
        for (int s3=0; s3<3; s3++){
            if (s3==2 && !has2) break;
            const bool ok = oks[s3];
            const int px = pxs[s3], so = sos[s3];
#pragma unroll
            for (int cgl=0; cgl<16; cgl+=4){
                float xv[4];
#pragma unroll
                for (int u2=0; u2<4; u2++)
                    xv[u2] = ok ? ip[(cgl+u2)*HW + px] : 0.f;
                if (MODE == 2){
                    float svv[4];
#pragma unroll
                    for (int u2=0; u2<4; u2++)
                        svv[u2] = ok ? skip[(cgl+u2)*HW + px] : 0.f;
#pragma unroll
                    for (int u2=0; u2<4; u2++){
                        float t = fmaxf(fmaf(xv[u2], s_a[cgl+u2], s_b[cgl+u2]) + svv[u2], 0.f);
                        s_in[(cgl+u2)*360 + so] = ok ? t : 0.f;
                    }
                } else if (MODE == 1){
#pragma unroll
                    for (int u2=0; u2<4; u2++){
                        float t = fmaxf(fmaf(xv[u2], s_a[cgl+u2], s_b[cgl+u2]), 0.f);
                        s_in[(cgl+u2)*360 + so] = ok ? t : 0.f;
                    }
                } else {
#pragma unroll
                    for (int u2=0; u2<4; u2++)
                        s_in[(cgl+u2)*360 + so] = xv[u2];
                }
            }
        }
        __syncthreads();

        // compute: 8 px x 4 co; weights amortized over 8 px
        const float* sbase = s_in + tz*36 + strip*8;
        const float* wb    = s_w  + cg*4;
#pragma unroll 2
        for (int ci=0; ci<16; ci++){
            const float* si    = sbase + ci*360;
            const float* wbase = wb    + ci*144;
#pragma unroll
            for (int kz=0; kz<3; kz++){
                const float* row = si + kz*36;
                float4 va = *reinterpret_cast<const float4*>(row);
                float4 vb = *reinterpret_cast<const float4*>(row + 4);
                float2 vc = *reinterpret_cast<const float2*>(row + 8);
                ull pv[10];
                pv[0]=pack2(va.x); pv[1]=pack2(va.y); pv[2]=pack2(va.z); pv[3]=pack2(va.w);
                pv[4]=pack2(vb.x); pv[5]=pack2(vb.y); pv[6]=pack2(vb.z); pv[7]=pack2(vb.w);
                pv[8]=pack2(vc.x); pv[9]=pack2(vc.y);
#pragma unroll
                for (int ky=0; ky<3; ky++){
                    ulonglong2 wq = *reinterpret_cast<const ulonglong2*>(wbase + (kz*3+ky)*16);
#pragma unroll
                    for (int py=0; py<8; py++){
                        fma2(acc[0][py], pv[ky+py], wq.x);
                        fma2(acc[1][py], pv[ky+py], wq.y);
                    }
                }
            }
        }
    }

    // epilogue: bias, vectorized store, fused stats
    const int oz  = tz0 + tz;
    const int oy0 = ty0 + strip*8;
    float* op = out + (size_t)osl*CHW + oz*128 + oy0;

    float sv[4], qv[4];
#pragma unroll
    for (int p=0; p<2; p++){
        const int c0 = cg*4 + 2*p, c1 = c0 + 1;
        const float b0 = bias[c0], b1 = bias[c1];
        float r0[8], r1[8];
#pragma unroll
        for (int py=0; py<8; py++){
            float x,y; unpack2(acc[p][py], x, y);
            r0[py] = x + b0;
            r1[py] = y + b1;
        }
        *reinterpret_cast<float4*>(op + c0*HW)     = make_float4(r0[0],r0[1],r0[2],r0[3]);
        *reinterpret_cast<float4*>(op + c0*HW + 4) = make_float4(r0[4],r0[5],r0[6],r0[7]);
        *reinterpret_cast<float4*>(op + c1*HW)     = make_float4(r1[0],r1[1],r1[2],r1[3]);
        *reinterpret_cast<float4*>(op + c1*HW + 4) = make_float4(r1[4],r1[5],r1[6],r1[7]);
        float s0=0.f,q0=0.f,s1=0.f,q1=0.f;
#pragma unroll
        for (int py=0; py<8; py++){
            s0 += r0[py]; q0 += r0[py]*r0[py];
            s1 += r1[py]; q1 += r1[py]*r1[py];
        }
        sv[2*p]=s0; qv[2*p]=q0; sv[2*p+1]=s1; qv[2*p+1]=q1;
    }
    // reduce over the 8 slots in this warp (lane bits 2..4)
#pragma unroll
    for (int o=16; o>=4; o>>=1){
#pragma unroll
        for (int j=0;j<4;j++){
            sv[j] += __shfl_xor_sync(0xffffffffu, sv[j], o);
            qv[j] += __shfl_xor_sync(0xffffffffu, qv[j], o);
        }
    }
    if ((tid & 31) < 4){
        const int wd = tid >> 5;
#pragma unroll
        for (int j=0;j<4;j++){
            s_red[wd][cg][j]   = sv[j];
            s_red[wd][cg][4+j] = qv[j];
        }
    }
    __syncthreads();
    if (tid < 32){
        const bool isq = tid >= 16;
        const int co = tid & 15;
        const int cgg = co >> 2, j = co & 3;
        const int off = isq ? (4+j) : j;
        float t = s_red[0][cgg][off] + s_red[1][cgg][off]
                + s_red[2][cgg][off] + s_red[3][cgg][off];
        t *= tp.mult[osl];
        atomicAdd(isq ? &stat_q[co] : &stat_s[co], t);
    }
}

// ---------------- fused final elementwise + forward projection ----------------
// final[sl] = relu( norm3(s3[sl]) + relu( norm1(s2[skm[sl]]) + V ) )
// out[c,0,z,u] = weighted slice sum at (z,y=u)
// out[c,1,z,u] = column sum over y of slice sel(u); u==0 sums only y=0..63
//   (reference fp32: x=+-3.9e-15 at uu=0, valid mask kills y in [64,127]).
__global__ __launch_bounds__(128) void forward_proj(
    const float* __restrict__ s3, const float* __restrict__ s2,
    const float* __restrict__ V, float* __restrict__ out)
{
    __shared__ float red[9][4];
    __shared__ float rs[9];
    const int c = blockIdx.x >> 7, z = blockIdx.x & 127;
    const int u = threadIdx.x;
    const int   skm[9]  = {0,1,2,2,2,2,2,3,4};
    const float mult[9] = {1.f,1.f,1.f,1.f,120.f,1.f,1.f,1.f,1.f};

    // inline stats finalize: bank1 (A2 output) and bank3 (B2 output)
    double sd1 = (double)g_sum[16+c], qd1 = (double)g_sumsq[16+c];
    double me1 = sd1/2097152.0;
    double i1d = 1.0/sqrt(qd1/2097152.0 - me1*me1 + 1e-5);
    const float i1 = (float)i1d, b1c = (float)(-me1*i1d);
    double sd3 = (double)g_sum[48+c], qd3 = (double)g_sumsq[48+c];
    double me3 = sd3/2097152.0;
    double i3d = 1.0/sqrt(qd3/2097152.0 - me3*me3 + 1e-5);
    const float i3 = (float)i3d, b3c = (float)(-me3*i3d);

    const int pix = z*128 + u;
    const float vb = V[c*HW + pix];

    float vals[9]; float s0 = 0.f;
#pragma unroll
    for (int sdx=0; sdx<9; sdx++){
        float t2 = s2[(size_t)(skm[sdx]*16 + c)*HW + pix];
        float sk = fmaxf(fmaf(t2, i1, b1c) + vb, 0.f);
        float t3 = s3[(size_t)(sdx*16 + c)*HW + pix];
        float fv = fmaxf(fmaf(t3, i3, b3c) + sk, 0.f);
        vals[sdx] = fv;
        s0 += mult[sdx]*fv;
    }
    out[(c*2+0)*HW + pix] = s0;

    const int lane = u & 31, wid = u >> 5;
#pragma unroll
    for (int sdx=0; sdx<9; sdx++){
        float v = vals[sdx];
#pragma unroll
        for (int o=16;o>0;o>>=1) v += __shfl_xor_sync(0xffffffffu, v, o);
        if (lane==0) red[sdx][wid]=v;
    }
    __syncthreads();
    if (u < 9) rs[u] = red[u][0]+red[u][1]+red[u][2]+red[u][3];
    __syncthreads();
    const int sl = (u<4) ? u : (u>123 ? u-119 : 4);
    float o1 = (u==0) ? (red[0][0]+red[0][1]) : rs[sl];
    out[(c*2+1)*HW + pix] = o1;
}

// ---------------- launch ----------------
extern "C" void kernel_launch(void* const* d_in, const int* in_sizes, int n_in,
                              void* d_out, int out_size)
{
    (void)in_sizes; (void)n_in; (void)out_size;
    const float* V    = (const float*)d_in[0];
    const float* w_a1 = (const float*)d_in[1];
    const float* b_a1 = (const float*)d_in[2];
    const float* w_a2 = (const float*)d_in[3];
    const float* b_a2 = (const float*)d_in[4];
    const float* w_b1 = (const float*)d_in[5];
    const float* b_b1 = (const float*)d_in[6];
    const float* w_b2 = (const float*)d_in[7];
    const float* b_b2 = (const float*)d_in[8];
    float* out = (float*)d_out;

    float *b1,*b2,*b3,*gsum,*gsq,*gwm;
    cudaGetSymbolAddress((void**)&b1,    g_b1);
    cudaGetSymbolAddress((void**)&b2,    g_b2);
    cudaGetSymbolAddress((void**)&b3,    g_b3);
    cudaGetSymbolAddress((void**)&gsum,  g_sum);
    cudaGetSymbolAddress((void**)&gsq,   g_sumsq);
    cudaGetSymbolAddress((void**)&gwm,   g_wm);

    // merged tap tables: (input slice, kx bitmask) per output slice
    Taps tA1 = {
        { {0,-1,-1},{0,-1,-1},{0,-1,-1} },
        { {6,0,0},{7,0,0},{3,0,0} },
        { 1.f,126.f,1.f }
    };
    Taps tA2 = {
        { {0,1,-1},{0,1,-1},{1,-1,-1},{1,2,-1},{1,2,-1} },
        { {2,4,0},{1,6,0},{7,0,0},{3,4,0},{1,2,0} },
        { 1.f,1.f,124.f,1.f,1.f }
    };
    Taps tB1 = {
        { {0,1,-1},{0,1,2},{1,2,-1},{2,-1,-1},{2,3,-1},{2,3,4},{3,4,-1} },
        { {2,4,0},{1,2,4},{1,6,0},{7,0,0},{3,4,0},{1,2,4},{1,2,0} },
        { 1.f,1.f,1.f,122.f,1.f,1.f,1.f }
    };
    Taps tB2 = {
        { {0,1,-1},{0,1,2},{1,2,3},{2,3,-1},{3,-1,-1},{3,4,-1},{3,4,5},{4,5,6},{5,6,-1} },
        { {2,4,0},{1,2,4},{1,2,4},{1,6,0},{7,0,0},{3,4,0},{1,2,4},{1,2,4},{1,2,0} },
        { 1.f,1.f,1.f,1.f,120.f,1.f,1.f,1.f,1.f }
    };

    MergeArgs ma;
    ma.w[0]=w_a1; ma.w[1]=w_a2; ma.w[2]=w_b1; ma.w[3]=w_b2;
    ma.tp[0]=tA1; ma.tp[1]=tA2; ma.tp[2]=tB1; ma.tp[3]=tB2;
    ma.n_osl[0]=3; ma.n_osl[1]=5; ma.n_osl[2]=7; ma.n_osl[3]=9;

    // setup: merge weights for all 4 stages + zero stats
    merge_weights<<<dim3(3,9,4),128>>>(ma);

    // A1: raw V (slice stride 0) -> b1 (3 slices), stats bank 0
    conv_stage<0><<<dim3(64,3),128>>>(V, 0, b1, gwm+0*WSTG, b_a1,
                                      nullptr, nullptr, nullptr,
                                      gsum+0, gsq+0, tA1);

    // A2: norm_relu(b1, bank0) -> b2 (5), stats bank 1
    conv_stage<1><<<dim3(64,5),128>>>(b1, CHW, b2, gwm+1*WSTG, b_a2,
                                      gsum+0, gsq+0, nullptr,
                                      gsum+16, gsq+16, tA2);

    // B1: relu(norm(b2, bank1) + V) -> b1 (7), stats bank 2
    conv_stage<2><<<dim3(64,7),128>>>(b2, CHW, b1, gwm+2*WSTG, b_b1,
                                      gsum+16, gsq+16, V,
                                      gsum+32, gsq+32, tB1);

    // B2: norm_relu(b1, bank2) -> b3 (9), stats bank 3
    conv_stage<1><<<dim3(64,9),128>>>(b1, CHW, b3, gwm+3*WSTG, b_b2,
                                      gsum+32, gsq+32, nullptr,
                                      gsum+48, gsq+48, tB2);

    // fused final norm+skip+relu + both projections (bank1+bank3 inline)
    forward_proj<<<16*128,128>>>(b3, b2, V, out);
}